// round 4
// baseline (speedup 1.0000x reference)
#include <cuda_runtime.h>
#include <cuda_fp16.h>
#include <cstdint>

// ============================================================================
// EdgeMLP: out = silu( silu(LN(concat(src,edge) @ W1 + b1)) @ W2 + b2 )
// E rows; in 192 (128 src + 64 edge), hid/out 128.
//
// Strategy (sm_103 via legacy PTX: tcgen05 is compile-blocked, harness PTX
// target is compute_103 without the 'a' feature set — so use mma.sync HMMA):
//   - persistent CTAs, 8 warps each; each warp owns independent 16-row groups
//   - weights pre-swizzled once into fragment-order smem (LDS.64 per mma)
//   - A fragments loaded directly from gmem (float2, full 32B sectors)
//   - epilogue (bias+LN+SiLU) entirely in registers: mma C-fragment layout
//     equals next mma A-fragment layout; row reduction = 2x shfl.bfly
//   - zero __syncthreads in main loop, no activation smem
// ============================================================================

static constexpr int NT1 = 16;   // 16 n8-tiles  -> N=128
static constexpr int KT1 = 12;   // 12 k16-tiles -> K=192
static constexpr int KT2 = 8;    // K=128
static constexpr float LN_EPS = 1e-5f;

// dynamic smem layout (bytes)
static constexpr int SM_W1F = 0;                         // 12*16*32 uint2 = 49152
static constexpr int SM_W2F = SM_W1F + KT1 * NT1 * 32 * 8;  // 49152
static constexpr int SM_B1  = SM_W2F + KT2 * NT1 * 32 * 8;  // 81920
static constexpr int SM_GM  = SM_B1 + 512;
static constexpr int SM_BT  = SM_GM + 512;
static constexpr int SM_B2  = SM_BT + 512;
static constexpr int SMEM_BYTES = SM_B2 + 512;           // 83968

__device__ __forceinline__ uint32_t packh2(float a, float b) {
    __half2 h = __floats2half2_rn(a, b);
    return *reinterpret_cast<uint32_t*>(&h);
}

__device__ __forceinline__ void mma16816(float c[4],
                                         uint32_t a0, uint32_t a1, uint32_t a2, uint32_t a3,
                                         uint32_t b0, uint32_t b1) {
    asm volatile(
        "mma.sync.aligned.m16n8k16.row.col.f32.f16.f16.f32 "
        "{%0,%1,%2,%3}, {%4,%5,%6,%7}, {%8,%9}, {%0,%1,%2,%3};"
        : "+f"(c[0]), "+f"(c[1]), "+f"(c[2]), "+f"(c[3])
        : "r"(a0), "r"(a1), "r"(a2), "r"(a3), "r"(b0), "r"(b1));
}

__device__ __forceinline__ float silu(float y) {
    return y / (1.0f + __expf(-y));
}

__global__ void __launch_bounds__(256, 1) edge_mlp_kernel(
    const float* __restrict__ src, const float* __restrict__ edg,
    const float* __restrict__ W1, const float* __restrict__ b1,
    const float* __restrict__ gma, const float* __restrict__ bta,
    const float* __restrict__ W2, const float* __restrict__ b2,
    float* __restrict__ out, int E, int n_groups)
{
    extern __shared__ char smem[];
    uint2* w1f = reinterpret_cast<uint2*>(smem + SM_W1F);
    uint2* w2f = reinterpret_cast<uint2*>(smem + SM_W2F);
    float* b1s = reinterpret_cast<float*>(smem + SM_B1);
    float* gms = reinterpret_cast<float*>(smem + SM_GM);
    float* bts = reinterpret_cast<float*>(smem + SM_BT);
    float* b2s = reinterpret_cast<float*>(smem + SM_B2);

    const int tid  = threadIdx.x;
    const int lane = tid & 31;
    const int wid  = tid >> 5;
    const int q    = lane >> 2;   // 0..7  (row within m16: q and q+8)
    const int c4   = lane & 3;    // 0..3  (col pair selector)

    // ---- one-time: params + fragment-order weight swizzle into smem ----
    for (int i = tid; i < 128; i += 256) {
        b1s[i] = b1[i];
        gms[i] = gma[i];
        bts[i] = bta[i];
        b2s[i] = b2[i];
    }
    // B fragment for mma.m16n8k16 col-major: lane holds
    //   b0 = {W[k][n], W[k+1][n]}, b1 = {W[k+8][n], W[k+9][n]}
    //   with k = 16*kt + 2*(lane&3), n = 8*nt + (lane>>2)
    for (int e = tid; e < KT1 * NT1 * 32; e += 256) {
        int l = e & 31, slot = e >> 5;
        int nt = slot & 15, kt = slot >> 4;
        int k = kt * 16 + 2 * (l & 3);
        int n = nt * 8 + (l >> 2);
        uint2 v;
        v.x = packh2(W1[k * 128 + n], W1[(k + 1) * 128 + n]);
        v.y = packh2(W1[(k + 8) * 128 + n], W1[(k + 9) * 128 + n]);
        w1f[e] = v;
    }
    for (int e = tid; e < KT2 * NT1 * 32; e += 256) {
        int l = e & 31, slot = e >> 5;
        int nt = slot & 15, kt = slot >> 4;
        int k = kt * 16 + 2 * (l & 3);
        int n = nt * 8 + (l >> 2);
        uint2 v;
        v.x = packh2(W2[k * 128 + n], W2[(k + 1) * 128 + n]);
        v.y = packh2(W2[(k + 8) * 128 + n], W2[(k + 9) * 128 + n]);
        w2f[e] = v;
    }
    __syncthreads();

    // ---- persistent loop: each warp processes independent 16-row groups ----
    const int warp_global = blockIdx.x * 8 + wid;
    const int warp_step   = gridDim.x * 8;

    for (int g = warp_global; g < n_groups; g += warp_step) {
        const int row0 = g * 16 + q;       // logical rows: row0, row0+8
        const int row1 = row0 + 8;
        // clamp loads for the (non-existent with E%16==0, but safe) tail
        const size_t r0 = (size_t)min(row0, E - 1);
        const size_t r1 = (size_t)min(row1, E - 1);

        // ================= GEMM1: [16x192] @ W1 -> c[16 nt][4] =================
        float c[NT1][4];
        #pragma unroll
        for (int nt = 0; nt < NT1; nt++) {
            c[nt][0] = 0.f; c[nt][1] = 0.f; c[nt][2] = 0.f; c[nt][3] = 0.f;
        }

        #pragma unroll
        for (int kt = 0; kt < KT1; kt++) {
            const float* bp = (kt < 8) ? src : edg;
            const int pitch = (kt < 8) ? 128 : 64;
            const int kk = ((kt < 8) ? kt * 16 : (kt - 8) * 16) + 2 * c4;
            float2 x00 = *reinterpret_cast<const float2*>(bp + r0 * pitch + kk);
            float2 x10 = *reinterpret_cast<const float2*>(bp + r1 * pitch + kk);
            float2 x01 = *reinterpret_cast<const float2*>(bp + r0 * pitch + kk + 8);
            float2 x11 = *reinterpret_cast<const float2*>(bp + r1 * pitch + kk + 8);
            uint32_t a0 = packh2(x00.x, x00.y);
            uint32_t a1 = packh2(x10.x, x10.y);
            uint32_t a2 = packh2(x01.x, x01.y);
            uint32_t a3 = packh2(x11.x, x11.y);
            const uint2* wrow = w1f + (kt * NT1) * 32 + lane;
            #pragma unroll
            for (int nt = 0; nt < NT1; nt++) {
                uint2 B = wrow[nt * 32];
                mma16816(c[nt], a0, a1, a2, a3, B.x, B.y);
            }
        }

        // ================= epilogue 1: +b1, LayerNorm, SiLU =================
        float s0 = 0.f, s1 = 0.f;
        #pragma unroll
        for (int nt = 0; nt < NT1; nt++) {
            float2 bb = *reinterpret_cast<const float2*>(b1s + 8 * nt + 2 * c4);
            c[nt][0] += bb.x; c[nt][1] += bb.y;
            c[nt][2] += bb.x; c[nt][3] += bb.y;
            s0 += c[nt][0] + c[nt][1];
            s1 += c[nt][2] + c[nt][3];
        }
        s0 += __shfl_xor_sync(0xffffffffu, s0, 1);
        s0 += __shfl_xor_sync(0xffffffffu, s0, 2);
        s1 += __shfl_xor_sync(0xffffffffu, s1, 1);
        s1 += __shfl_xor_sync(0xffffffffu, s1, 2);
        const float mu0 = s0 * (1.f / 128.f);
        const float mu1 = s1 * (1.f / 128.f);

        float v0 = 0.f, v1 = 0.f;
        #pragma unroll
        for (int nt = 0; nt < NT1; nt++) {
            float d0 = c[nt][0] - mu0, d1 = c[nt][1] - mu0;
            float d2 = c[nt][2] - mu1, d3 = c[nt][3] - mu1;
            v0 += d0 * d0 + d1 * d1;
            v1 += d2 * d2 + d3 * d3;
        }
        v0 += __shfl_xor_sync(0xffffffffu, v0, 1);
        v0 += __shfl_xor_sync(0xffffffffu, v0, 2);
        v1 += __shfl_xor_sync(0xffffffffu, v1, 1);
        v1 += __shfl_xor_sync(0xffffffffu, v1, 2);
        const float rs0 = rsqrtf(v0 * (1.f / 128.f) + LN_EPS);
        const float rs1 = rsqrtf(v1 * (1.f / 128.f) + LN_EPS);

        // C fragment (n8-tiles 2j, 2j+1) == A fragment (k16-tile j) layout:
        uint32_t a2f[KT2][4];
        #pragma unroll
        for (int nt = 0; nt < NT1; nt++) {
            float2 gg = *reinterpret_cast<const float2*>(gms + 8 * nt + 2 * c4);
            float2 bb = *reinterpret_cast<const float2*>(bts + 8 * nt + 2 * c4);
            float y0 = silu((c[nt][0] - mu0) * rs0 * gg.x + bb.x);
            float y1 = silu((c[nt][1] - mu0) * rs0 * gg.y + bb.y);
            float y2 = silu((c[nt][2] - mu1) * rs1 * gg.x + bb.x);
            float y3 = silu((c[nt][3] - mu1) * rs1 * gg.y + bb.y);
            const int kt = nt >> 1;
            if ((nt & 1) == 0) {
                a2f[kt][0] = packh2(y0, y1);
                a2f[kt][1] = packh2(y2, y3);
            } else {
                a2f[kt][2] = packh2(y0, y1);
                a2f[kt][3] = packh2(y2, y3);
            }
        }

        // ================= GEMM2: [16x128] @ W2 -> d[16 nt][4] =================
        float d[NT1][4];
        #pragma unroll
        for (int nt = 0; nt < NT1; nt++) {
            d[nt][0] = 0.f; d[nt][1] = 0.f; d[nt][2] = 0.f; d[nt][3] = 0.f;
        }
        #pragma unroll
        for (int kt = 0; kt < KT2; kt++) {
            const uint2* wrow = w2f + (kt * NT1) * 32 + lane;
            #pragma unroll
            for (int nt = 0; nt < NT1; nt++) {
                uint2 B = wrow[nt * 32];
                mma16816(d[nt], a2f[kt][0], a2f[kt][1], a2f[kt][2], a2f[kt][3], B.x, B.y);
            }
        }

        // ================= epilogue 2: +b2, SiLU, store =================
        const bool val0 = (row0 < E);
        const bool val1 = (row1 < E);
        #pragma unroll
        for (int nt = 0; nt < NT1; nt++) {
            float2 bb = *reinterpret_cast<const float2*>(b2s + 8 * nt + 2 * c4);
            float2 o0, o1;
            o0.x = silu(d[nt][0] + bb.x);
            o0.y = silu(d[nt][1] + bb.y);
            o1.x = silu(d[nt][2] + bb.x);
            o1.y = silu(d[nt][3] + bb.y);
            const int col = 8 * nt + 2 * c4;
            if (val0) *reinterpret_cast<float2*>(out + (size_t)row0 * 128 + col) = o0;
            if (val1) *reinterpret_cast<float2*>(out + (size_t)row1 * 128 + col) = o1;
        }
    }
}

// ===================== launch =====================
extern "C" void kernel_launch(void* const* d_in, const int* in_sizes, int n_in,
                              void* d_out, int out_size)
{
    (void)n_in; (void)out_size;
    const float* src = (const float*)d_in[0];
    const float* edg = (const float*)d_in[1];
    const float* W1  = (const float*)d_in[2];
    const float* b1  = (const float*)d_in[3];
    const float* gma = (const float*)d_in[4];
    const float* bta = (const float*)d_in[5];
    const float* W2  = (const float*)d_in[6];
    const float* b2  = (const float*)d_in[7];
    float* out = (float*)d_out;

    const int E = in_sizes[0] / 128;
    const int n_groups = (E + 15) / 16;

    cudaFuncSetAttribute(edge_mlp_kernel,
                         cudaFuncAttributeMaxDynamicSharedMemorySize, SMEM_BYTES);
    edge_mlp_kernel<<<152, 256, SMEM_BYTES>>>(src, edg, W1, b1, gma, bta, W2, b2,
                                              out, E, n_groups);
}

// round 5
// speedup vs baseline: 1.3712x; 1.3712x over previous
#include <cuda_runtime.h>
#include <cuda_fp16.h>
#include <cstdint>

// ============================================================================
// EdgeMLP: out = silu( silu(LN(concat(src,edge) @ W1 + b1)) @ W2 + b2 )
// E rows; in 192 (128 src + 64 edge), hid/out 128.
//
// R5: occupancy fix. R4 profile: occ 12.5% (1 CTA/SM, 160 regs), issue 27%,
// nothing saturated -> latency bound. Changes:
//   - __launch_bounds__(256, 2): 2 CTAs/SM (16 warps/SM), regs capped at 128;
//     accumulator array explicitly reused across both GEMMs to avoid spills
//   - B fragments stored as uint4 pairs: one LDS.128 feeds 2 mmas (halves
//     shared-load instruction count)
//   - everything else unchanged: warp-owned 16-row groups, weights swizzled
//     once to fragment order in smem, epilogue fully in registers,
//     no __syncthreads in main loop
// ============================================================================

static constexpr int NT1 = 16;   // 16 n8-tiles  -> N=128
static constexpr int NP1 = 8;    // 8 n16 pairs
static constexpr int KT1 = 12;   // 12 k16-tiles -> K=192
static constexpr int KT2 = 8;    // K=128
static constexpr float LN_EPS = 1e-5f;

// dynamic smem layout (bytes)
static constexpr int SM_W1F = 0;                              // 12*8*32 uint4 = 49152
static constexpr int SM_W2F = SM_W1F + KT1 * NP1 * 32 * 16;   // 49152
static constexpr int SM_B1  = SM_W2F + KT2 * NP1 * 32 * 16;   // 81920
static constexpr int SM_GM  = SM_B1 + 512;
static constexpr int SM_BT  = SM_GM + 512;
static constexpr int SM_B2  = SM_BT + 512;
static constexpr int SMEM_BYTES = SM_B2 + 512;                // 83968

__device__ __forceinline__ uint32_t packh2(float a, float b) {
    __half2 h = __floats2half2_rn(a, b);
    return *reinterpret_cast<uint32_t*>(&h);
}

__device__ __forceinline__ void mma16816(float c[4],
                                         uint32_t a0, uint32_t a1, uint32_t a2, uint32_t a3,
                                         uint32_t b0, uint32_t b1) {
    asm volatile(
        "mma.sync.aligned.m16n8k16.row.col.f32.f16.f16.f32 "
        "{%0,%1,%2,%3}, {%4,%5,%6,%7}, {%8,%9}, {%0,%1,%2,%3};"
        : "+f"(c[0]), "+f"(c[1]), "+f"(c[2]), "+f"(c[3])
        : "r"(a0), "r"(a1), "r"(a2), "r"(a3), "r"(b0), "r"(b1));
}

__device__ __forceinline__ float silu(float y) {
    return y / (1.0f + __expf(-y));
}

__global__ void __launch_bounds__(256, 2) edge_mlp_kernel(
    const float* __restrict__ src, const float* __restrict__ edg,
    const float* __restrict__ W1, const float* __restrict__ b1,
    const float* __restrict__ gma, const float* __restrict__ bta,
    const float* __restrict__ W2, const float* __restrict__ b2,
    float* __restrict__ out, int E, int n_groups)
{
    extern __shared__ char smem[];
    uint4* w1f = reinterpret_cast<uint4*>(smem + SM_W1F);
    uint4* w2f = reinterpret_cast<uint4*>(smem + SM_W2F);
    float* b1s = reinterpret_cast<float*>(smem + SM_B1);
    float* gms = reinterpret_cast<float*>(smem + SM_GM);
    float* bts = reinterpret_cast<float*>(smem + SM_BT);
    float* b2s = reinterpret_cast<float*>(smem + SM_B2);

    const int tid  = threadIdx.x;
    const int lane = tid & 31;
    const int wid  = tid >> 5;
    const int q    = lane >> 2;   // 0..7  (row within m16: q and q+8)
    const int c4   = lane & 3;    // 0..3  (col pair selector)

    // ---- one-time: params + fragment-order weight swizzle into smem ----
    for (int i = tid; i < 128; i += 256) {
        b1s[i] = b1[i];
        gms[i] = gma[i];
        bts[i] = bta[i];
        b2s[i] = b2[i];
    }
    // Paired B fragments for mma.m16n8k16 col-major. Slot (kt, np) holds for
    // each lane a uint4:
    //   .x = {W[k][n0],   W[k+1][n0]},  .y = {W[k+8][n0], W[k+9][n0]}   (nt=2np)
    //   .z = {W[k][n1],   W[k+1][n1]},  .w = {W[k+8][n1], W[k+9][n1]}   (nt=2np+1)
    //   k = 16*kt + 2*(lane&3), n0 = 16*np + (lane>>2), n1 = n0 + 8
    for (int e = tid; e < KT1 * NP1 * 32; e += 256) {
        int l = e & 31, slot = e >> 5;
        int np = slot & 7, kt = slot >> 3;
        int k = kt * 16 + 2 * (l & 3);
        int n0 = np * 16 + (l >> 2);
        int n1 = n0 + 8;
        uint4 v;
        v.x = packh2(W1[k * 128 + n0], W1[(k + 1) * 128 + n0]);
        v.y = packh2(W1[(k + 8) * 128 + n0], W1[(k + 9) * 128 + n0]);
        v.z = packh2(W1[k * 128 + n1], W1[(k + 1) * 128 + n1]);
        v.w = packh2(W1[(k + 8) * 128 + n1], W1[(k + 9) * 128 + n1]);
        w1f[e] = v;
    }
    for (int e = tid; e < KT2 * NP1 * 32; e += 256) {
        int l = e & 31, slot = e >> 5;
        int np = slot & 7, kt = slot >> 3;
        int k = kt * 16 + 2 * (l & 3);
        int n0 = np * 16 + (l >> 2);
        int n1 = n0 + 8;
        uint4 v;
        v.x = packh2(W2[k * 128 + n0], W2[(k + 1) * 128 + n0]);
        v.y = packh2(W2[(k + 8) * 128 + n0], W2[(k + 9) * 128 + n0]);
        v.z = packh2(W2[k * 128 + n1], W2[(k + 1) * 128 + n1]);
        v.w = packh2(W2[(k + 8) * 128 + n1], W2[(k + 9) * 128 + n1]);
        w2f[e] = v;
    }
    __syncthreads();

    // ---- persistent loop: each warp processes independent 16-row groups ----
    const int warp_global = blockIdx.x * 8 + wid;
    const int warp_step   = gridDim.x * 8;

    for (int g = warp_global; g < n_groups; g += warp_step) {
        const int row0 = g * 16 + q;       // logical rows: row0, row0+8
        const int row1 = row0 + 8;
        const size_t r0 = (size_t)min(row0, E - 1);
        const size_t r1 = (size_t)min(row1, E - 1);

        // ================= GEMM1: [16x192] @ W1 -> acc[16 nt][4] =================
        float acc[NT1][4];
        #pragma unroll
        for (int nt = 0; nt < NT1; nt++) {
            acc[nt][0] = 0.f; acc[nt][1] = 0.f; acc[nt][2] = 0.f; acc[nt][3] = 0.f;
        }

        #pragma unroll
        for (int kt = 0; kt < KT1; kt++) {
            const float* bp = (kt < 8) ? src : edg;
            const int pitch = (kt < 8) ? 128 : 64;
            const int kk = ((kt < 8) ? kt * 16 : (kt - 8) * 16) + 2 * c4;
            float2 x00 = *reinterpret_cast<const float2*>(bp + r0 * pitch + kk);
            float2 x10 = *reinterpret_cast<const float2*>(bp + r1 * pitch + kk);
            float2 x01 = *reinterpret_cast<const float2*>(bp + r0 * pitch + kk + 8);
            float2 x11 = *reinterpret_cast<const float2*>(bp + r1 * pitch + kk + 8);
            uint32_t a0 = packh2(x00.x, x00.y);
            uint32_t a1 = packh2(x10.x, x10.y);
            uint32_t a2 = packh2(x01.x, x01.y);
            uint32_t a3 = packh2(x11.x, x11.y);
            const uint4* wrow = w1f + (kt * NP1) * 32 + lane;
            #pragma unroll
            for (int np = 0; np < NP1; np++) {
                uint4 B = wrow[np * 32];
                mma16816(acc[2 * np],     a0, a1, a2, a3, B.x, B.y);
                mma16816(acc[2 * np + 1], a0, a1, a2, a3, B.z, B.w);
            }
        }

        // ================= epilogue 1: +b1, LayerNorm, SiLU =================
        float s0 = 0.f, s1 = 0.f;
        #pragma unroll
        for (int nt = 0; nt < NT1; nt++) {
            float2 bb = *reinterpret_cast<const float2*>(b1s + 8 * nt + 2 * c4);
            acc[nt][0] += bb.x; acc[nt][1] += bb.y;
            acc[nt][2] += bb.x; acc[nt][3] += bb.y;
            s0 += acc[nt][0] + acc[nt][1];
            s1 += acc[nt][2] + acc[nt][3];
        }
        s0 += __shfl_xor_sync(0xffffffffu, s0, 1);
        s0 += __shfl_xor_sync(0xffffffffu, s0, 2);
        s1 += __shfl_xor_sync(0xffffffffu, s1, 1);
        s1 += __shfl_xor_sync(0xffffffffu, s1, 2);
        const float mu0 = s0 * (1.f / 128.f);
        const float mu1 = s1 * (1.f / 128.f);

        float v0 = 0.f, v1 = 0.f;
        #pragma unroll
        for (int nt = 0; nt < NT1; nt++) {
            float d0 = acc[nt][0] - mu0, d1 = acc[nt][1] - mu0;
            float d2 = acc[nt][2] - mu1, d3 = acc[nt][3] - mu1;
            v0 += d0 * d0 + d1 * d1;
            v1 += d2 * d2 + d3 * d3;
        }
        v0 += __shfl_xor_sync(0xffffffffu, v0, 1);
        v0 += __shfl_xor_sync(0xffffffffu, v0, 2);
        v1 += __shfl_xor_sync(0xffffffffu, v1, 1);
        v1 += __shfl_xor_sync(0xffffffffu, v1, 2);
        const float rs0 = rsqrtf(v0 * (1.f / 128.f) + LN_EPS);
        const float rs1 = rsqrtf(v1 * (1.f / 128.f) + LN_EPS);

        // C fragment (n8-tiles 2j, 2j+1) == A fragment (k16-tile j) layout:
        uint32_t a2f[KT2][4];
        #pragma unroll
        for (int nt = 0; nt < NT1; nt++) {
            float2 gg = *reinterpret_cast<const float2*>(gms + 8 * nt + 2 * c4);
            float2 bb = *reinterpret_cast<const float2*>(bts + 8 * nt + 2 * c4);
            float y0 = silu((acc[nt][0] - mu0) * rs0 * gg.x + bb.x);
            float y1 = silu((acc[nt][1] - mu0) * rs0 * gg.y + bb.y);
            float y2 = silu((acc[nt][2] - mu1) * rs1 * gg.x + bb.x);
            float y3 = silu((acc[nt][3] - mu1) * rs1 * gg.y + bb.y);
            const int kt = nt >> 1;
            if ((nt & 1) == 0) {
                a2f[kt][0] = packh2(y0, y1);
                a2f[kt][1] = packh2(y2, y3);
            } else {
                a2f[kt][2] = packh2(y0, y1);
                a2f[kt][3] = packh2(y2, y3);
            }
        }

        // ================= GEMM2: [16x128] @ W2 -> acc (reused) =================
        #pragma unroll
        for (int nt = 0; nt < NT1; nt++) {
            acc[nt][0] = 0.f; acc[nt][1] = 0.f; acc[nt][2] = 0.f; acc[nt][3] = 0.f;
        }
        #pragma unroll
        for (int kt = 0; kt < KT2; kt++) {
            const uint4* wrow = w2f + (kt * NP1) * 32 + lane;
            #pragma unroll
            for (int np = 0; np < NP1; np++) {
                uint4 B = wrow[np * 32];
                mma16816(acc[2 * np],     a2f[kt][0], a2f[kt][1], a2f[kt][2], a2f[kt][3], B.x, B.y);
                mma16816(acc[2 * np + 1], a2f[kt][0], a2f[kt][1], a2f[kt][2], a2f[kt][3], B.z, B.w);
            }
        }

        // ================= epilogue 2: +b2, SiLU, store =================
        const bool val0 = (row0 < E);
        const bool val1 = (row1 < E);
        #pragma unroll
        for (int nt = 0; nt < NT1; nt++) {
            float2 bb = *reinterpret_cast<const float2*>(b2s + 8 * nt + 2 * c4);
            float2 o0, o1;
            o0.x = silu(acc[nt][0] + bb.x);
            o0.y = silu(acc[nt][1] + bb.y);
            o1.x = silu(acc[nt][2] + bb.x);
            o1.y = silu(acc[nt][3] + bb.y);
            const int col = 8 * nt + 2 * c4;
            if (val0) *reinterpret_cast<float2*>(out + (size_t)row0 * 128 + col) = o0;
            if (val1) *reinterpret_cast<float2*>(out + (size_t)row1 * 128 + col) = o1;
        }
    }
}

// ===================== launch =====================
extern "C" void kernel_launch(void* const* d_in, const int* in_sizes, int n_in,
                              void* d_out, int out_size)
{
    (void)n_in; (void)out_size;
    const float* src = (const float*)d_in[0];
    const float* edg = (const float*)d_in[1];
    const float* W1  = (const float*)d_in[2];
    const float* b1  = (const float*)d_in[3];
    const float* gma = (const float*)d_in[4];
    const float* bta = (const float*)d_in[5];
    const float* W2  = (const float*)d_in[6];
    const float* b2  = (const float*)d_in[7];
    float* out = (float*)d_out;

    const int E = in_sizes[0] / 128;
    const int n_groups = (E + 15) / 16;

    cudaFuncSetAttribute(edge_mlp_kernel,
                         cudaFuncAttributeMaxDynamicSharedMemorySize, SMEM_BYTES);
    edge_mlp_kernel<<<304, 256, SMEM_BYTES>>>(src, edg, W1, b1, gma, bta, W2, b2,
                                              out, E, n_groups);
}